// round 13
// baseline (speedup 1.0000x reference)
#include <cuda_runtime.h>
#include <cuda_fp16.h>
#include <cstdint>

// Problem dims
#define BT 16384   // B*T = 8*2048
#define TSEQ 2048
#define DD 512
#define HH 128
#define NK 7
#define FF 512
#define KF 3584    // NK*FF

// Scratch (allocation-free rule: __device__ globals)
__device__ float g_rs[BT];
__device__ __half g_h16[BT * HH];            // fp16 h (written by gemm1)
__device__ __half g_y16[BT * FF];            // fp16 pre-LN y (written by gemm2)
__device__ __half g_W1h[HH * DD];            // W1T fp16  [h][d]
__device__ __half g_B16[NK * FF * HH];       // W2T fp16, [k][f][h]

// ---------------------------------------------------------------------------
// Helpers (base sm_103-safe: ldmatrix / mma.sync / cp.async only)
// ---------------------------------------------------------------------------
__device__ __forceinline__ uint32_t smem_u32(const void* p) {
    uint32_t a;
    asm("{ .reg .u64 t; cvta.to.shared.u64 t, %1; cvt.u32.u64 %0, t; }" : "=r"(a) : "l"(p));
    return a;
}
__device__ __forceinline__ void ldsm_x4(uint32_t a, uint32_t* r) {
    asm volatile("ldmatrix.sync.aligned.m8n8.x4.shared.b16 {%0,%1,%2,%3}, [%4];"
                 : "=r"(r[0]), "=r"(r[1]), "=r"(r[2]), "=r"(r[3]) : "r"(a));
}
__device__ __forceinline__ void mma16816(float* c, const uint32_t* a,
                                         uint32_t b0, uint32_t b1) {
    asm volatile("mma.sync.aligned.m16n8k16.row.col.f32.f16.f16.f32 "
                 "{%0,%1,%2,%3}, {%4,%5,%6,%7}, {%8,%9}, {%0,%1,%2,%3};"
                 : "+f"(c[0]), "+f"(c[1]), "+f"(c[2]), "+f"(c[3])
                 : "r"(a[0]), "r"(a[1]), "r"(a[2]), "r"(a[3]), "r"(b0), "r"(b1));
}
#define CP_ASYNC16(dst, src) \
    asm volatile("cp.async.cg.shared.global [%0], [%1], 16;" :: "r"(dst), "l"(src))
#define CP_COMMIT() asm volatile("cp.async.commit_group;" ::: "memory")
#define CP_WAIT(n)  asm volatile("cp.async.wait_group %0;" :: "n"(n) : "memory")
#define SWZ(o) ((o) ^ (((o) >> 3) & 0x70))

// ---------------------------------------------------------------------------
// prep_w1: W1T only (must precede gemm1)
// ---------------------------------------------------------------------------
__global__ __launch_bounds__(256) void prep_w1_kernel(const float* __restrict__ W1) {
    int idx = blockIdx.x * 256 + threadIdx.x;   // 65536, d fastest
    int h = idx >> 9, d = idx & 511;
    g_W1h[idx] = __float2half_rn(W1[(size_t)d * HH + h]);
}

// ---------------------------------------------------------------------------
// GEMM1 (+ W2 prep on blocks >= 256): h = relu(x @ W1 + b1); also rowsum.
// gemm CTAs: 64 rows x 128 cols(H), 256 thr, warp 32x32, K=512 in 8 chunks.
// A-path software-pipelined: LDG chunk c+2 regs during MMAs of chunk c.
// ---------------------------------------------------------------------------
#define G1_STAGE 24576
#define G1_TOTAL 49152
#define G1_GEMM_BLOCKS (BT / 64)     // 256
__global__ __launch_bounds__(256, 2) void gemm1_mma_kernel(
    const float* __restrict__ x, const float* __restrict__ b1,
    const float* __restrict__ W2) {
    extern __shared__ char smem[];
    int tid = threadIdx.x;

    if (blockIdx.x >= G1_GEMM_BLOCKS) {
        int idx = (blockIdx.x - G1_GEMM_BLOCKS) * 256 + tid;  // h fastest
        int h = idx & 127;
        int rest = idx >> 7;
        int f = rest & 511, k = rest >> 9;
        g_B16[idx] = __float2half_rn(W2[(size_t)h * KF + k * FF + f]);
        return;
    }

    uint32_t sb = smem_u32(smem);
    int warp = tid >> 5, lane = tid & 31;
    int wm = warp & 1, wn = warp >> 1;
    int rowBase = blockIdx.x * 64;

    int a_row[4], a_c4[4];
#pragma unroll
    for (int i = 0; i < 4; i++) {
        int lin = i * 256 + tid;
        a_row[i] = lin >> 4;
        a_c4[i] = lin & 15;
    }

    float acc[2][4][4];
#pragma unroll
    for (int a = 0; a < 2; a++)
#pragma unroll
        for (int b = 0; b < 4; b++)
#pragma unroll
            for (int cc = 0; cc < 4; cc++) acc[a][b][cc] = 0.f;

    float4 areg[4];
    auto loadA = [&](int c) {
        int p0 = c * 64;
#pragma unroll
        for (int i = 0; i < 4; i++)
            areg[i] = *(const float4*)(x + (size_t)(rowBase + a_row[i]) * DD + p0 + a_c4[i] * 4);
    };
    auto storeA = [&](int s) {
        char* a_p = smem + s * G1_STAGE;
#pragma unroll
        for (int i = 0; i < 4; i++) {
            __half2 p0h = __floats2half2_rn(areg[i].x, areg[i].y);
            __half2 p1h = __floats2half2_rn(areg[i].z, areg[i].w);
            uint2 w;
            w.x = *(uint32_t*)&p0h; w.y = *(uint32_t*)&p1h;
            *(uint2*)(a_p + SWZ(a_row[i] * 128 + a_c4[i] * 8)) = w;
        }
    };
    auto issueB = [&](int c, int s) {
        uint32_t b_s = sb + s * G1_STAGE + 8192;
        int p0 = c * 64;
#pragma unroll
        for (int i = 0; i < 4; i++) {
            int lin = i * 256 + tid;
            int row = lin >> 3, c16 = lin & 7;
            CP_ASYNC16(b_s + SWZ(row * 128 + c16 * 16),
                       g_W1h + (size_t)row * DD + p0 + c16 * 8);
        }
        CP_COMMIT();
    };

    issueB(0, 0);
    loadA(0);
    storeA(0);
    loadA(1);

    // rowsum for this CTA's 64 rows; warp w -> rows w*8..w*8+7
    {
#pragma unroll
        for (int r8 = 0; r8 < 8; r8++) {
            int row = rowBase + warp * 8 + r8;
            const float4* xr = (const float4*)(x + (size_t)row * DD);
            float s = 0.f;
#pragma unroll
            for (int j = lane; j < DD / 4; j += 32) {
                float4 v = xr[j];
                s += (v.x + v.y) + (v.z + v.w);
            }
#pragma unroll
            for (int o = 16; o; o >>= 1) s += __shfl_xor_sync(0xffffffffu, s, o);
            if (lane == 0) g_rs[row] = s;
        }
    }

    for (int c = 0; c < 8; c++) {
        int s = c & 1;
        CP_WAIT(0);
        __syncthreads();
        if (c < 7) {
            issueB(c + 1, s ^ 1);
            storeA(s ^ 1);
        }
        if (c < 6) loadA(c + 2);
        uint32_t a_s = sb + s * G1_STAGE;
        uint32_t b_s = a_s + 8192;
        int r = lane & 15, half = lane >> 4;
#pragma unroll
        for (int k16 = 0; k16 < 4; k16++) {
            int kc = k16 * 32 + half * 16;
            uint32_t ah[2][4], bh[2][4];
#pragma unroll
            for (int mt = 0; mt < 2; mt++)
                ldsm_x4(a_s + SWZ((wm * 32 + mt * 16 + r) * 128 + kc), ah[mt]);
#pragma unroll
            for (int g = 0; g < 2; g++)
                ldsm_x4(b_s + SWZ((wn * 32 + g * 16 + r) * 128 + kc), bh[g]);
#pragma unroll
            for (int mt = 0; mt < 2; mt++)
#pragma unroll
                for (int nt = 0; nt < 4; nt++) {
                    int g = nt >> 1, i2 = nt & 1;
                    mma16816(acc[mt][nt], ah[mt], bh[g][i2], bh[g][i2 + 2]);
                }
        }
    }

    int r = lane >> 2, cp2 = (lane & 3) * 2;
#pragma unroll
    for (int mt = 0; mt < 2; mt++) {
        int row0 = wm * 32 + mt * 16 + r;
        size_t off0 = (size_t)(rowBase + row0) * HH;
        size_t off1 = off0 + 8 * HH;
#pragma unroll
        for (int nt = 0; nt < 4; nt++) {
            int col = wn * 32 + nt * 8 + cp2;
            float2 bb = *(const float2*)(b1 + col);
            __half2 h0 = __floats2half2_rn(fmaxf(acc[mt][nt][0] + bb.x, 0.f),
                                           fmaxf(acc[mt][nt][1] + bb.y, 0.f));
            __half2 h1 = __floats2half2_rn(fmaxf(acc[mt][nt][2] + bb.x, 0.f),
                                           fmaxf(acc[mt][nt][3] + bb.y, 0.f));
            *(uint32_t*)(g_h16 + off0 + col) = *(uint32_t*)&h0;
            *(uint32_t*)(g_h16 + off1 + col) = *(uint32_t*)&h1;
        }
    }
}

// ---------------------------------------------------------------------------
// GEMM2: y16 = x + sum_k diag(rs_k) * (h @ W2_k) + rs-window bias   (pre-LN)
// CTA: 128 rows x 128 f, 512 thr, 16 warps (4Mx4N), warp tile 32x32
// A (h fp16, K=128) loaded ONCE; B per-tap TRIPLE-buffered (32KB/stage).
// Epilogue stores fp16 y to g_y16 (half the traffic; L2-resident for ln).
// ---------------------------------------------------------------------------
#define G2_SMRS 0
#define G2_SMB2 1024        // 7*128 floats
#define G2_SMA  8192        // A 32KB (two 64-col subtiles)
#define G2_SMB  40960       // 3 stages x 32KB
#define G2_TOTAL 139264
__global__ __launch_bounds__(512, 1) void gemm2_mma_kernel(
    const float* __restrict__ x, const float* __restrict__ b2) {
    extern __shared__ char smem[];
    uint32_t sb = smem_u32(smem);
    int tid = threadIdx.x;
    int warp = tid >> 5, lane = tid & 31;
    int wm = warp & 3, wn = warp >> 2;
    int rowBase = blockIdx.y * 128;
    int fBase = blockIdx.x * 128;

    float* rs_s = (float*)(smem + G2_SMRS);
    float* b2_s = (float*)(smem + G2_SMB2);
    int bstart = (rowBase / TSEQ) * TSEQ;
    if (tid < 136) {
        int gi = rowBase + tid - 3;
        float v = 0.f;
        if (tid < 134 && gi >= bstart && gi < bstart + TSEQ) v = g_rs[gi];
        rs_s[tid] = v;
    }
    for (int i = tid; i < NK * 128; i += 512)
        b2_s[i] = b2[(i >> 7) * FF + fBase + (i & 127)];

    {   // A: 128x128 fp16 via cp.async, two 64-col subtiles
        uint32_t a_s = sb + G2_SMA;
#pragma unroll
        for (int i = 0; i < 4; i++) {
            int lin = i * 512 + tid;
            int row = lin >> 4, c16 = lin & 15;
            uint32_t dsw = (c16 >> 3) * 16384 + SWZ(row * 128 + (c16 & 7) * 16);
            CP_ASYNC16(a_s + dsw, g_h16 + (size_t)(rowBase + row) * HH + c16 * 8);
        }
    }
    auto issueB = [&](int tap, int s) {
        uint32_t b_s = sb + G2_SMB + s * 32768;
#pragma unroll
        for (int i = 0; i < 2; i++) {
            int lin = i * 512 + tid;
            int row = lin >> 3, c16 = lin & 7;
            uint32_t dsw = SWZ(row * 128 + c16 * 16);
            CP_ASYNC16(b_s + dsw,
                       g_B16 + ((size_t)tap * FF + fBase + row) * HH + c16 * 8);
            CP_ASYNC16(b_s + 16384 + dsw,
                       g_B16 + ((size_t)tap * FF + fBase + row) * HH + 64 + c16 * 8);
        }
        CP_COMMIT();
    };
    issueB(0, 0);
    issueB(1, 1);

    float acc2[2][4][4];
#pragma unroll
    for (int a = 0; a < 2; a++)
#pragma unroll
        for (int b = 0; b < 4; b++)
#pragma unroll
            for (int cc = 0; cc < 4; cc++) acc2[a][b][cc] = 0.f;

    int r = lane & 15, half = lane >> 4;
    int rr = lane >> 2;

    for (int tap = 0; tap < NK; tap++) {
        int s = tap - (tap / 3) * 3;
        __syncthreads();
        if (tap + 2 < NK) {
            int s2 = (tap + 2) - ((tap + 2) / 3) * 3;
            issueB(tap + 2, s2);
        }
        if (tap < 5) { CP_WAIT(2); } else if (tap == 5) { CP_WAIT(1); } else { CP_WAIT(0); }
        __syncthreads();

        float acc[2][4][4];
#pragma unroll
        for (int a = 0; a < 2; a++)
#pragma unroll
            for (int b = 0; b < 4; b++)
#pragma unroll
                for (int cc = 0; cc < 4; cc++) acc[a][b][cc] = 0.f;

        uint32_t a_s = sb + G2_SMA;
        uint32_t b_s = sb + G2_SMB + s * 32768;
#pragma unroll
        for (int k16 = 0; k16 < 8; k16++) {
            int kcb = k16 * 32 + half * 16;
            uint32_t sub = (kcb >> 7) * 16384;
            int within = kcb & 127;
            uint32_t ah[2][4], bh[2][4];
#pragma unroll
            for (int mt = 0; mt < 2; mt++)
                ldsm_x4(a_s + sub + SWZ((wm * 32 + mt * 16 + r) * 128 + within), ah[mt]);
#pragma unroll
            for (int g = 0; g < 2; g++)
                ldsm_x4(b_s + sub + SWZ((wn * 32 + g * 16 + r) * 128 + within), bh[g]);
#pragma unroll
            for (int mt = 0; mt < 2; mt++)
#pragma unroll
                for (int nt = 0; nt < 4; nt++) {
                    int g = nt >> 1, i2 = nt & 1;
                    mma16816(acc[mt][nt], ah[mt], bh[g][i2], bh[g][i2 + 2]);
                }
        }
#pragma unroll
        for (int mt = 0; mt < 2; mt++) {
            int rloc = wm * 32 + mt * 16 + rr;
            float rv0 = rs_s[rloc + tap];
            float rv1 = rs_s[rloc + 8 + tap];
#pragma unroll
            for (int nt = 0; nt < 4; nt++) {
                acc2[mt][nt][0] = fmaf(rv0, acc[mt][nt][0], acc2[mt][nt][0]);
                acc2[mt][nt][1] = fmaf(rv0, acc[mt][nt][1], acc2[mt][nt][1]);
                acc2[mt][nt][2] = fmaf(rv1, acc[mt][nt][2], acc2[mt][nt][2]);
                acc2[mt][nt][3] = fmaf(rv1, acc[mt][nt][3], acc2[mt][nt][3]);
            }
        }
    }

    // epilogue: + rs-window bias + residual -> fp16 y to g_y16
    int cp2 = (lane & 3) * 2;
#pragma unroll
    for (int mt = 0; mt < 2; mt++) {
        int row0 = wm * 32 + mt * 16 + rr;
        int row1 = row0 + 8;
        float rv0[NK], rv1[NK];
#pragma unroll
        for (int k = 0; k < NK; k++) { rv0[k] = rs_s[row0 + k]; rv1[k] = rs_s[row1 + k]; }
        const float* x0 = x + (size_t)(rowBase + row0) * DD + fBase;
        const float* x1 = x0 + 8 * DD;
        __half* y0 = g_y16 + (size_t)(rowBase + row0) * FF + fBase;
        __half* y1 = y0 + 8 * FF;
#pragma unroll
        for (int nt = 0; nt < 4; nt++) {
            int col = wn * 32 + nt * 8 + cp2;
            float b00 = 0.f, b01 = 0.f, b10 = 0.f, b11 = 0.f;
#pragma unroll
            for (int k = 0; k < NK; k++) {
                float2 bb = *(const float2*)&b2_s[k * 128 + col];
                b00 = fmaf(rv0[k], bb.x, b00);
                b01 = fmaf(rv0[k], bb.y, b01);
                b10 = fmaf(rv1[k], bb.x, b10);
                b11 = fmaf(rv1[k], bb.y, b11);
            }
            float2 xv0 = *(const float2*)(x0 + col);
            float2 xv1 = *(const float2*)(x1 + col);
            __half2 h0 = __floats2half2_rn(acc2[mt][nt][0] + xv0.x + b00,
                                           acc2[mt][nt][1] + xv0.y + b01);
            __half2 h1 = __floats2half2_rn(acc2[mt][nt][2] + xv1.x + b10,
                                           acc2[mt][nt][3] + xv1.y + b11);
            *(uint32_t*)(y0 + col) = *(uint32_t*)&h0;
            *(uint32_t*)(y1 + col) = *(uint32_t*)&h1;
        }
    }
}

// ---------------------------------------------------------------------------
// LayerNorm(eps=1e-3) + relu: read fp16 y (L2-hot), write fp32 out.
// Warp per row, 8 rows per 256-thr block. Lane reads 2 uint4 (16 halves).
// ---------------------------------------------------------------------------
__global__ __launch_bounds__(256) void ln_kernel(
    float* __restrict__ out, const float* __restrict__ gamma,
    const float* __restrict__ beta) {
    int warp = threadIdx.x >> 5, lane = threadIdx.x & 31;
    int row = blockIdx.x * 8 + warp;
    const uint4* yr = (const uint4*)(g_y16 + (size_t)row * FF);

    uint4 ya = yr[lane];          // halves [lane*8, lane*8+8)
    uint4 yb = yr[lane + 32];     // halves [(lane+32)*8, ...)

    float va[8], vb[8];
    {
        const uint32_t* pa = (const uint32_t*)&ya;
        const uint32_t* pb = (const uint32_t*)&yb;
#pragma unroll
        for (int i = 0; i < 4; i++) {
            float2 fa = __half22float2(*(const __half2*)&pa[i]);
            float2 fb = __half22float2(*(const __half2*)&pb[i]);
            va[i * 2] = fa.x; va[i * 2 + 1] = fa.y;
            vb[i * 2] = fb.x; vb[i * 2 + 1] = fb.y;
        }
    }
    float s = 0.f, q = 0.f;
#pragma unroll
    for (int i = 0; i < 8; i++) {
        s += va[i] + vb[i];
        q += va[i] * va[i] + vb[i] * vb[i];
    }
#pragma unroll
    for (int o = 16; o; o >>= 1) {
        s += __shfl_xor_sync(0xffffffffu, s, o);
        q += __shfl_xor_sync(0xffffffffu, q, o);
    }
    float mean = s * (1.f / FF);
    float inv = rsqrtf(q * (1.f / FF) - mean * mean + 1e-3f);

    float* orow = out + (size_t)row * FF;
    const float4* g4 = (const float4*)gamma;
    const float4* b4 = (const float4*)beta;
#pragma unroll
    for (int half = 0; half < 2; half++) {
        const float* v = half ? vb : va;
        int base = (half ? (lane + 32) : lane) * 8;
#pragma unroll
        for (int j = 0; j < 2; j++) {
            float4 g = __ldg(g4 + base / 4 + j);
            float4 b = __ldg(b4 + base / 4 + j);
            float4 o;
            o.x = fmaxf((v[j * 4 + 0] - mean) * inv * g.x + b.x, 0.f);
            o.y = fmaxf((v[j * 4 + 1] - mean) * inv * g.y + b.y, 0.f);
            o.z = fmaxf((v[j * 4 + 2] - mean) * inv * g.z + b.z, 0.f);
            o.w = fmaxf((v[j * 4 + 3] - mean) * inv * g.w + b.w, 0.f);
            *(float4*)(orow + base + j * 4) = o;
        }
    }
}

// ---------------------------------------------------------------------------
extern "C" void kernel_launch(void* const* d_in, const int* in_sizes, int n_in,
                              void* d_out, int out_size) {
    const float* x     = (const float*)d_in[0];
    const float* W1    = (const float*)d_in[1];
    const float* b1    = (const float*)d_in[2];
    const float* W2    = (const float*)d_in[3];
    const float* b2    = (const float*)d_in[4];
    const float* gamma = (const float*)d_in[5];
    const float* beta  = (const float*)d_in[6];
    float* out = (float*)d_out;

    cudaFuncSetAttribute(gemm1_mma_kernel,
                         cudaFuncAttributeMaxDynamicSharedMemorySize, G1_TOTAL);
    cudaFuncSetAttribute(gemm2_mma_kernel,
                         cudaFuncAttributeMaxDynamicSharedMemorySize, G2_TOTAL);

    prep_w1_kernel<<<256, 256>>>(W1);
    gemm1_mma_kernel<<<G1_GEMM_BLOCKS + (NK * FF * HH) / 256, 256, G1_TOTAL>>>(x, b1, W2);
    gemm2_mma_kernel<<<dim3(FF / 128, BT / 128), 512, G2_TOTAL>>>(x, b2);
    ln_kernel<<<BT / 8, 256>>>(out, gamma, beta);
}

// round 14
// speedup vs baseline: 1.0611x; 1.0611x over previous
#include <cuda_runtime.h>
#include <cuda_fp16.h>
#include <cstdint>

// Problem dims
#define BT 16384   // B*T = 8*2048
#define TSEQ 2048
#define DD 512
#define HH 128
#define NK 7
#define FF 512
#define KF 3584    // NK*FF

// Scratch (allocation-free rule: __device__ globals)
__device__ float g_rs[BT];
__device__ __half g_h16[BT * HH];            // fp16 h (written by gemm1)
__device__ __half g_W1h[HH * DD];            // W1T fp16  [h][d]
__device__ __half g_B16[NK * FF * HH];       // W2T fp16, [k][f][h]

// ---------------------------------------------------------------------------
// Helpers (base sm_103-safe: ldmatrix / mma.sync / cp.async only)
// ---------------------------------------------------------------------------
__device__ __forceinline__ uint32_t smem_u32(const void* p) {
    uint32_t a;
    asm("{ .reg .u64 t; cvta.to.shared.u64 t, %1; cvt.u32.u64 %0, t; }" : "=r"(a) : "l"(p));
    return a;
}
__device__ __forceinline__ void ldsm_x4(uint32_t a, uint32_t* r) {
    asm volatile("ldmatrix.sync.aligned.m8n8.x4.shared.b16 {%0,%1,%2,%3}, [%4];"
                 : "=r"(r[0]), "=r"(r[1]), "=r"(r[2]), "=r"(r[3]) : "r"(a));
}
__device__ __forceinline__ void mma16816(float* c, const uint32_t* a,
                                         uint32_t b0, uint32_t b1) {
    asm volatile("mma.sync.aligned.m16n8k16.row.col.f32.f16.f16.f32 "
                 "{%0,%1,%2,%3}, {%4,%5,%6,%7}, {%8,%9}, {%0,%1,%2,%3};"
                 : "+f"(c[0]), "+f"(c[1]), "+f"(c[2]), "+f"(c[3])
                 : "r"(a[0]), "r"(a[1]), "r"(a[2]), "r"(a[3]), "r"(b0), "r"(b1));
}
#define CP_ASYNC16(dst, src) \
    asm volatile("cp.async.cg.shared.global [%0], [%1], 16;" :: "r"(dst), "l"(src))
#define CP_COMMIT() asm volatile("cp.async.commit_group;" ::: "memory")
#define CP_WAIT(n)  asm volatile("cp.async.wait_group %0;" :: "n"(n) : "memory")
#define SWZ(o) ((o) ^ (((o) >> 3) & 0x70))

// ---------------------------------------------------------------------------
// prep_w1: W1T only (must precede gemm1)
// ---------------------------------------------------------------------------
__global__ __launch_bounds__(256) void prep_w1_kernel(const float* __restrict__ W1) {
    int idx = blockIdx.x * 256 + threadIdx.x;   // 65536, d fastest
    int h = idx >> 9, d = idx & 511;
    g_W1h[idx] = __float2half_rn(W1[(size_t)d * HH + h]);
}

// ---------------------------------------------------------------------------
// GEMM1 (+ W2 prep on blocks >= 256): h = relu(x @ W1 + b1); also rowsum.
// gemm CTAs: 64 rows x 128 cols(H), 256 thr, warp 32x32, K=512 in 8 chunks.
// A-path software-pipelined: LDG chunk c+2 regs during MMAs of chunk c.
// ---------------------------------------------------------------------------
#define G1_STAGE 24576
#define G1_TOTAL 49152
#define G1_GEMM_BLOCKS (BT / 64)     // 256
__global__ __launch_bounds__(256, 2) void gemm1_mma_kernel(
    const float* __restrict__ x, const float* __restrict__ b1,
    const float* __restrict__ W2) {
    extern __shared__ char smem[];
    int tid = threadIdx.x;

    if (blockIdx.x >= G1_GEMM_BLOCKS) {
        int idx = (blockIdx.x - G1_GEMM_BLOCKS) * 256 + tid;  // h fastest
        int h = idx & 127;
        int rest = idx >> 7;
        int f = rest & 511, k = rest >> 9;
        g_B16[idx] = __float2half_rn(W2[(size_t)h * KF + k * FF + f]);
        return;
    }

    uint32_t sb = smem_u32(smem);
    int warp = tid >> 5, lane = tid & 31;
    int wm = warp & 1, wn = warp >> 1;
    int rowBase = blockIdx.x * 64;

    int a_row[4], a_c4[4];
#pragma unroll
    for (int i = 0; i < 4; i++) {
        int lin = i * 256 + tid;
        a_row[i] = lin >> 4;
        a_c4[i] = lin & 15;
    }

    float acc[2][4][4];
#pragma unroll
    for (int a = 0; a < 2; a++)
#pragma unroll
        for (int b = 0; b < 4; b++)
#pragma unroll
            for (int cc = 0; cc < 4; cc++) acc[a][b][cc] = 0.f;

    float4 areg[4];
    auto loadA = [&](int c) {
        int p0 = c * 64;
#pragma unroll
        for (int i = 0; i < 4; i++)
            areg[i] = *(const float4*)(x + (size_t)(rowBase + a_row[i]) * DD + p0 + a_c4[i] * 4);
    };
    auto storeA = [&](int s) {
        char* a_p = smem + s * G1_STAGE;
#pragma unroll
        for (int i = 0; i < 4; i++) {
            __half2 p0h = __floats2half2_rn(areg[i].x, areg[i].y);
            __half2 p1h = __floats2half2_rn(areg[i].z, areg[i].w);
            uint2 w;
            w.x = *(uint32_t*)&p0h; w.y = *(uint32_t*)&p1h;
            *(uint2*)(a_p + SWZ(a_row[i] * 128 + a_c4[i] * 8)) = w;
        }
    };
    auto issueB = [&](int c, int s) {
        uint32_t b_s = sb + s * G1_STAGE + 8192;
        int p0 = c * 64;
#pragma unroll
        for (int i = 0; i < 4; i++) {
            int lin = i * 256 + tid;
            int row = lin >> 3, c16 = lin & 7;
            CP_ASYNC16(b_s + SWZ(row * 128 + c16 * 16),
                       g_W1h + (size_t)row * DD + p0 + c16 * 8);
        }
        CP_COMMIT();
    };

    issueB(0, 0);
    loadA(0);
    storeA(0);
    loadA(1);

    // rowsum for this CTA's 64 rows; warp w -> rows w*8..w*8+7
    {
#pragma unroll
        for (int r8 = 0; r8 < 8; r8++) {
            int row = rowBase + warp * 8 + r8;
            const float4* xr = (const float4*)(x + (size_t)row * DD);
            float s = 0.f;
#pragma unroll
            for (int j = lane; j < DD / 4; j += 32) {
                float4 v = xr[j];
                s += (v.x + v.y) + (v.z + v.w);
            }
#pragma unroll
            for (int o = 16; o; o >>= 1) s += __shfl_xor_sync(0xffffffffu, s, o);
            if (lane == 0) g_rs[row] = s;
        }
    }

    for (int c = 0; c < 8; c++) {
        int s = c & 1;
        CP_WAIT(0);
        __syncthreads();
        if (c < 7) {
            issueB(c + 1, s ^ 1);
            storeA(s ^ 1);
        }
        if (c < 6) loadA(c + 2);
        uint32_t a_s = sb + s * G1_STAGE;
        uint32_t b_s = a_s + 8192;
        int r = lane & 15, half = lane >> 4;
#pragma unroll
        for (int k16 = 0; k16 < 4; k16++) {
            int kc = k16 * 32 + half * 16;
            uint32_t ah[2][4], bh[2][4];
#pragma unroll
            for (int mt = 0; mt < 2; mt++)
                ldsm_x4(a_s + SWZ((wm * 32 + mt * 16 + r) * 128 + kc), ah[mt]);
#pragma unroll
            for (int g = 0; g < 2; g++)
                ldsm_x4(b_s + SWZ((wn * 32 + g * 16 + r) * 128 + kc), bh[g]);
#pragma unroll
            for (int mt = 0; mt < 2; mt++)
#pragma unroll
                for (int nt = 0; nt < 4; nt++) {
                    int g = nt >> 1, i2 = nt & 1;
                    mma16816(acc[mt][nt], ah[mt], bh[g][i2], bh[g][i2 + 2]);
                }
        }
    }

    int r = lane >> 2, cp2 = (lane & 3) * 2;
#pragma unroll
    for (int mt = 0; mt < 2; mt++) {
        int row0 = wm * 32 + mt * 16 + r;
        size_t off0 = (size_t)(rowBase + row0) * HH;
        size_t off1 = off0 + 8 * HH;
#pragma unroll
        for (int nt = 0; nt < 4; nt++) {
            int col = wn * 32 + nt * 8 + cp2;
            float2 bb = *(const float2*)(b1 + col);
            __half2 h0 = __floats2half2_rn(fmaxf(acc[mt][nt][0] + bb.x, 0.f),
                                           fmaxf(acc[mt][nt][1] + bb.y, 0.f));
            __half2 h1 = __floats2half2_rn(fmaxf(acc[mt][nt][2] + bb.x, 0.f),
                                           fmaxf(acc[mt][nt][3] + bb.y, 0.f));
            *(uint32_t*)(g_h16 + off0 + col) = *(uint32_t*)&h0;
            *(uint32_t*)(g_h16 + off1 + col) = *(uint32_t*)&h1;
        }
    }
}

// ---------------------------------------------------------------------------
// GEMM2: out = x + sum_k diag(rs_k) * (h @ W2_k) + rs-window bias   (pre-LN)
// CTA: 128 rows x 128 f, 512 thr, 16 warps (4Mx4N), warp tile 32x32
// A (h fp16, K=128) loaded ONCE; B per-tap 4-stage ring, ONE barrier per tap.
// ---------------------------------------------------------------------------
#define G2_SMRS 0
#define G2_SMB2 1024        // 7*128 floats
#define G2_SMA  8192        // A 32KB (two 64-col subtiles)
#define G2_SMB  40960       // 4 stages x 32KB
#define G2_TOTAL 172032
__global__ __launch_bounds__(512, 1) void gemm2_mma_kernel(
    const float* __restrict__ x, const float* __restrict__ b2,
    float* __restrict__ out) {
    extern __shared__ char smem[];
    uint32_t sb = smem_u32(smem);
    int tid = threadIdx.x;
    int warp = tid >> 5, lane = tid & 31;
    int wm = warp & 3, wn = warp >> 2;
    int rowBase = blockIdx.y * 128;
    int fBase = blockIdx.x * 128;

    float* rs_s = (float*)(smem + G2_SMRS);
    float* b2_s = (float*)(smem + G2_SMB2);
    int bstart = (rowBase / TSEQ) * TSEQ;
    if (tid < 136) {
        int gi = rowBase + tid - 3;
        float v = 0.f;
        if (tid < 134 && gi >= bstart && gi < bstart + TSEQ) v = g_rs[gi];
        rs_s[tid] = v;
    }
    for (int i = tid; i < NK * 128; i += 512)
        b2_s[i] = b2[(i >> 7) * FF + fBase + (i & 127)];

    {   // A: 128x128 fp16 via cp.async, two 64-col subtiles
        uint32_t a_s = sb + G2_SMA;
#pragma unroll
        for (int i = 0; i < 4; i++) {
            int lin = i * 512 + tid;
            int row = lin >> 4, c16 = lin & 15;
            uint32_t dsw = (c16 >> 3) * 16384 + SWZ(row * 128 + (c16 & 7) * 16);
            CP_ASYNC16(a_s + dsw, g_h16 + (size_t)(rowBase + row) * HH + c16 * 8);
        }
    }
    auto issueB = [&](int tap) {
        uint32_t b_s = sb + G2_SMB + (tap & 3) * 32768;
#pragma unroll
        for (int i = 0; i < 2; i++) {
            int lin = i * 512 + tid;
            int row = lin >> 3, c16 = lin & 7;
            uint32_t dsw = SWZ(row * 128 + c16 * 16);
            CP_ASYNC16(b_s + dsw,
                       g_B16 + ((size_t)tap * FF + fBase + row) * HH + c16 * 8);
            CP_ASYNC16(b_s + 16384 + dsw,
                       g_B16 + ((size_t)tap * FF + fBase + row) * HH + 64 + c16 * 8);
        }
        CP_COMMIT();
    };
    // prologue: A+B0 (group0), B1 (group1), B2 (group2)
    issueB(0);
    issueB(1);
    issueB(2);

    float acc2[2][4][4];
#pragma unroll
    for (int a = 0; a < 2; a++)
#pragma unroll
        for (int b = 0; b < 4; b++)
#pragma unroll
            for (int cc = 0; cc < 4; cc++) acc2[a][b][cc] = 0.f;

    int r = lane & 15, half = lane >> 4;
    int rr = lane >> 2;

    for (int tap = 0; tap < NK; tap++) {
        // B(tap) ready when outstanding groups <= (last_issued - tap)
        if (tap <= 4) { CP_WAIT(2); } else if (tap == 5) { CP_WAIT(1); } else { CP_WAIT(0); }
        __syncthreads();   // publish B(tap) (+A at tap0); all warps past tap-1 MMAs
        if (tap + 3 < NK) issueB(tap + 3);  // into stage consumed at tap-1: safe

        float acc[2][4][4];
#pragma unroll
        for (int a = 0; a < 2; a++)
#pragma unroll
            for (int b = 0; b < 4; b++)
#pragma unroll
                for (int cc = 0; cc < 4; cc++) acc[a][b][cc] = 0.f;

        uint32_t a_s = sb + G2_SMA;
        uint32_t b_s = sb + G2_SMB + (tap & 3) * 32768;
#pragma unroll
        for (int k16 = 0; k16 < 8; k16++) {
            int kcb = k16 * 32 + half * 16;
            uint32_t sub = (kcb >> 7) * 16384;
            int within = kcb & 127;
            uint32_t ah[2][4], bh[2][4];
#pragma unroll
            for (int mt = 0; mt < 2; mt++)
                ldsm_x4(a_s + sub + SWZ((wm * 32 + mt * 16 + r) * 128 + within), ah[mt]);
#pragma unroll
            for (int g = 0; g < 2; g++)
                ldsm_x4(b_s + sub + SWZ((wn * 32 + g * 16 + r) * 128 + within), bh[g]);
#pragma unroll
            for (int mt = 0; mt < 2; mt++)
#pragma unroll
                for (int nt = 0; nt < 4; nt++) {
                    int g = nt >> 1, i2 = nt & 1;
                    mma16816(acc[mt][nt], ah[mt], bh[g][i2], bh[g][i2 + 2]);
                }
        }
#pragma unroll
        for (int mt = 0; mt < 2; mt++) {
            int rloc = wm * 32 + mt * 16 + rr;
            float rv0 = rs_s[rloc + tap];
            float rv1 = rs_s[rloc + 8 + tap];
#pragma unroll
            for (int nt = 0; nt < 4; nt++) {
                acc2[mt][nt][0] = fmaf(rv0, acc[mt][nt][0], acc2[mt][nt][0]);
                acc2[mt][nt][1] = fmaf(rv0, acc[mt][nt][1], acc2[mt][nt][1]);
                acc2[mt][nt][2] = fmaf(rv1, acc[mt][nt][2], acc2[mt][nt][2]);
                acc2[mt][nt][3] = fmaf(rv1, acc[mt][nt][3], acc2[mt][nt][3]);
            }
        }
    }

    // epilogue: + rs-window bias + residual -> y (pre-LN) to out
    int cp2 = (lane & 3) * 2;
#pragma unroll
    for (int mt = 0; mt < 2; mt++) {
        int row0 = wm * 32 + mt * 16 + rr;
        int row1 = row0 + 8;
        float rv0[NK], rv1[NK];
#pragma unroll
        for (int k = 0; k < NK; k++) { rv0[k] = rs_s[row0 + k]; rv1[k] = rs_s[row1 + k]; }
        const float* x0 = x + (size_t)(rowBase + row0) * DD + fBase;
        const float* x1 = x0 + 8 * DD;
        float* o0 = out + (size_t)(rowBase + row0) * FF + fBase;
        float* o1 = o0 + 8 * FF;
#pragma unroll
        for (int nt = 0; nt < 4; nt++) {
            int col = wn * 32 + nt * 8 + cp2;
            float b00 = 0.f, b01 = 0.f, b10 = 0.f, b11 = 0.f;
#pragma unroll
            for (int k = 0; k < NK; k++) {
                float2 bb = *(const float2*)&b2_s[k * 128 + col];
                b00 = fmaf(rv0[k], bb.x, b00);
                b01 = fmaf(rv0[k], bb.y, b01);
                b10 = fmaf(rv1[k], bb.x, b10);
                b11 = fmaf(rv1[k], bb.y, b11);
            }
            float2 xv0 = *(const float2*)(x0 + col);
            float2 xv1 = *(const float2*)(x1 + col);
            float2 v0, v1;
            v0.x = acc2[mt][nt][0] + xv0.x + b00;
            v0.y = acc2[mt][nt][1] + xv0.y + b01;
            v1.x = acc2[mt][nt][2] + xv1.x + b10;
            v1.y = acc2[mt][nt][3] + xv1.y + b11;
            *(float2*)(o0 + col) = v0;
            *(float2*)(o1 + col) = v1;
        }
    }
}

// ---------------------------------------------------------------------------
// LayerNorm(eps=1e-3) + relu, in place. Warp per row, streaming hints:
// __ldcs on y read (read-once), __stcs on out write (streaming).
// ---------------------------------------------------------------------------
__global__ __launch_bounds__(256) void ln_kernel(
    float* __restrict__ out, const float* __restrict__ gamma,
    const float* __restrict__ beta) {
    int warp = threadIdx.x >> 5, lane = threadIdx.x & 31;
    int row = blockIdx.x * 8 + warp;
    float4* orow = (float4*)(out + (size_t)row * FF);

    float4 v[4];
    float s = 0.f, q = 0.f;
#pragma unroll
    for (int i = 0; i < 4; i++) {
        v[i] = __ldcs(orow + lane + i * 32);
        s += (v[i].x + v[i].y) + (v[i].z + v[i].w);
        q += (v[i].x * v[i].x + v[i].y * v[i].y) +
             (v[i].z * v[i].z + v[i].w * v[i].w);
    }
#pragma unroll
    for (int o = 16; o; o >>= 1) {
        s += __shfl_xor_sync(0xffffffffu, s, o);
        q += __shfl_xor_sync(0xffffffffu, q, o);
    }
    float mean = s * (1.f / FF);
    float inv = rsqrtf(q * (1.f / FF) - mean * mean + 1e-3f);

    const float4* g4 = (const float4*)gamma;
    const float4* b4 = (const float4*)beta;
#pragma unroll
    for (int i = 0; i < 4; i++) {
        float4 g = __ldg(g4 + lane + i * 32);
        float4 b = __ldg(b4 + lane + i * 32);
        float4 o;
        o.x = fmaxf((v[i].x - mean) * inv * g.x + b.x, 0.f);
        o.y = fmaxf((v[i].y - mean) * inv * g.y + b.y, 0.f);
        o.z = fmaxf((v[i].z - mean) * inv * g.z + b.z, 0.f);
        o.w = fmaxf((v[i].w - mean) * inv * g.w + b.w, 0.f);
        __stcs(orow + lane + i * 32, o);
    }
}

// ---------------------------------------------------------------------------
extern "C" void kernel_launch(void* const* d_in, const int* in_sizes, int n_in,
                              void* d_out, int out_size) {
    const float* x     = (const float*)d_in[0];
    const float* W1    = (const float*)d_in[1];
    const float* b1    = (const float*)d_in[2];
    const float* W2    = (const float*)d_in[3];
    const float* b2    = (const float*)d_in[4];
    const float* gamma = (const float*)d_in[5];
    const float* beta  = (const float*)d_in[6];
    float* out = (float*)d_out;

    cudaFuncSetAttribute(gemm1_mma_kernel,
                         cudaFuncAttributeMaxDynamicSharedMemorySize, G1_TOTAL);
    cudaFuncSetAttribute(gemm2_mma_kernel,
                         cudaFuncAttributeMaxDynamicSharedMemorySize, G2_TOTAL);

    prep_w1_kernel<<<256, 256>>>(W1);
    gemm1_mma_kernel<<<G1_GEMM_BLOCKS + (NK * FF * HH) / 256, 256, G1_TOTAL>>>(x, b1, W2);
    gemm2_mma_kernel<<<dim3(FF / 128, BT / 128), 512, G2_TOTAL>>>(x, b2, out);
    ln_kernel<<<BT / 8, 256>>>(out, gamma, beta);
}